// round 13
// baseline (speedup 1.0000x reference)
#include <cuda_runtime.h>

#define B_  4
#define O_  32
#define C_  32
#define HW_ 32
#define P_  5
#define T_  (C_ * 9)      // 288 taps per output channel
#define EPSF 1e-6f
#define TSP_ 36           // pair-row stride in u64 (rows 16B-aligned)

typedef unsigned long long u64;

__device__ __forceinline__ u64 pk(float lo, float hi) {
    u64 r; asm("mov.b64 %0, {%1, %2};" : "=l"(r) : "f"(lo), "f"(hi)); return r;
}
__device__ __forceinline__ void upk(float& lo, float& hi, u64 v) {
    asm("mov.b64 {%0, %1}, %2;" : "=f"(lo), "=f"(hi) : "l"(v));
}
__device__ __forceinline__ u64 fma2(u64 a, u64 b, u64 c) {
    u64 d; asm("fma.rn.f32x2 %0, %1, %2, %3;" : "=l"(d) : "l"(a), "l"(b), "l"(c));
    return d;
}
__device__ __forceinline__ u64 add2(u64 a, u64 b) {
    u64 d; asm("add.rn.f32x2 %0, %1, %2;" : "=l"(d) : "l"(a), "l"(b));
    return d;
}
// Per-half saturate of a packed pair via rt-1 immediate-form FFMA.SAT.
// sat(rn(u)) == clamp to [0,1]; validated vs reference (rel_err ~3e-7).
__device__ __forceinline__ u64 sat2(u64 u) {
    u64 s;
    asm("{\n\t"
        ".reg .f32 lo, hi;\n\t"
        "mov.b64 {lo, hi}, %1;\n\t"
        "fma.rn.sat.f32 lo, lo, 0f3F800000, 0f00000000;\n\t"
        "fma.rn.sat.f32 hi, hi, 0f3F800000, 0f00000000;\n\t"
        "mov.b64 %0, {lo, hi};\n\t"
        "}" : "=l"(s) : "l"(u));
    return s;
}

// ---------------------------------------------------------------------------
// Packed vertical-pair kernel (R12 WIN) + occupancy push:
//  - __launch_bounds__(256,5): 48-reg cap -> 5 resident blocks/SM (40 warps).
//    R12 measured fma pipe at 42% (FFMA2 is FULL-RATE packed) => kernel is
//    latency-bound at occ 32.6%; more warps is now the right lever.
//  - JIT coefficient loads inside the tap: load each segment's (inv,nq) pair
//    right before use; peak live regs drop ~12 so the 48-reg cap holds
//    without spills. LDS count unchanged (uniform broadcasts).
// Pixels paired VERTICALLY at stride 4 (rows r, r+4 of an 8-row strip); all
// operands natively u64. Math/2px-seg: FFMA2 + 2x FFMA.SAT(rt-1) + FFMA2.
// Grid: 512 = (b, o, 8-row strip). Block: 256 = 8 warps; warp = 4 channels,
// 8 px/thread (4 vertical pairs).
// ---------------------------------------------------------------------------
__global__ __launch_bounds__(256, 5) void pc_fused(const float* __restrict__ x,
                                                   const float* __restrict__ pos,
                                                   const float* __restrict__ val,
                                                   float* __restrict__ out) {
    const int blk = blockIdx.x;
    const int quarter = blk & 3;           // 8-row strip
    const int o = (blk >> 2) & 31;
    const int b = blk >> 7;
    const int y0 = quarter * 8;

    __shared__ ulonglong2 s_tab[T_ * 6];            // 27648 B (u64-dup coeffs)
    __shared__ float      s_v0[T_];                 // 1152 B
    __shared__ __align__(16) u64 s_x[8][6 * TSP_];  // 13824 B (packed tiles)
    __shared__ float      s_bias;
    u64* red = &s_x[0][0];                 // reduction aliases s_x (8192 B)

    const int tid = threadIdx.x;

    // ---- Phase 0: sort + duplicated coefficient tables ----
    const float* pbase = pos + o * (T_ * P_);
    const float* vbase = val + o * (T_ * P_);
#pragma unroll
    for (int rep = 0; rep < 2; rep++) {
        int ot = tid + rep * 256;
        if (ot < T_) {
            float p[P_], v[P_];
#pragma unroll
            for (int k = 0; k < P_; k++) { p[k] = pbase[ot * P_ + k]; v[k] = vbase[ot * P_ + k]; }
#define CE(a, bb) do { if (p[a] > p[bb]) { float t0 = p[a]; p[a] = p[bb]; p[bb] = t0; \
                                           float t1 = v[a]; v[a] = v[bb]; v[bb] = t1; } } while (0)
            CE(0,1); CE(3,4); CE(2,4); CE(2,3); CE(1,4); CE(0,3); CE(0,2); CE(1,3); CE(1,2);
#undef CE
            float* tf = (float*)(s_tab + ot * 6);   // 24 floats per tap
#pragma unroll
            for (int k = 0; k < 4; k++) {
                float den = p[k + 1] - p[k] + EPSF;
                float inv = 1.0f / den;
                float nq  = -p[k] * inv;
                float dv  = v[k + 1] - v[k];
                tf[4 * k + 0] = inv; tf[4 * k + 1] = inv;
                tf[4 * k + 2] = nq;  tf[4 * k + 3] = nq;
                tf[16 + 2 * k + 0] = dv; tf[16 + 2 * k + 1] = dv;
            }
            s_v0[ot] = v[0];
        }
    }
    __syncthreads();

    if (tid < 32) {        // bias = sum_t v0
        float s = 0.0f;
#pragma unroll
        for (int k = 0; k < 9; k++) s += s_v0[tid + k * 32];
#pragma unroll
        for (int off = 16; off > 0; off >>= 1) s += __shfl_down_sync(0xffffffffu, s, off);
        if (tid == 0) s_bias = s;
    }
    __syncthreads();

    // ---- Phase 1 ----
    const int warp = tid >> 5;
    const int lane = tid & 31;
    const int rl   = lane >> 3;            // 0..3: pair row group (rows rl, rl+4)
    const int xg   = (lane & 7) * 4;       // 0,4,...,28

    u64 acc0 = 0ull, acc1 = 0ull, acc2 = 0ull, acc3 = 0ull;

    const float* xb = x + b * (C_ * HW_ * HW_);
    const int cBase = warp * 4;            // 4 channels per warp
    const float* xc = xb + cBase * (HW_ * HW_);
    u64* tile = s_x[warp];

// Fill packed tile: pair-row k holds (x[y0+k-1], x[y0+k+3]) at col scol-1.
#define FILL(XC) do {                                                      \
    const float* xp_ = (XC);                                               \
    _Pragma("unroll")                                                      \
    for (int k = 0; k < 6; k++) {                                          \
        int gyL_ = y0 + k - 1;                                             \
        int gyH_ = y0 + k + 3;                                             \
        int gx_ = lane - 1;                                                \
        bool cok_ = (gx_ >= 0);                                            \
        float lo_ = (cok_ && gyL_ >= 0 && gyL_ < HW_) ? xp_[gyL_ * HW_ + gx_] : 0.0f; \
        float hi_ = (cok_ && gyH_ < HW_) ? xp_[gyH_ * HW_ + gx_] : 0.0f;   \
        tile[k * TSP_ + lane] = pk(lo_, hi_);                              \
        if (lane < 2) {                                                    \
            int gx2_ = 31 + lane;                                          \
            bool c2_ = (gx2_ < HW_);                                       \
            float lo2_ = (c2_ && gyL_ >= 0 && gyL_ < HW_) ? xp_[gyL_ * HW_ + gx2_] : 0.0f; \
            float hi2_ = (c2_ && gyH_ < HW_) ? xp_[gyH_ * HW_ + gx2_] : 0.0f; \
            tile[k * TSP_ + 32 + lane] = pk(lo2_, hi2_);                   \
        }                                                                  \
    } } while (0)

// One segment, 4 pixel-pairs: coefficients loaded JIT (c = {inv2, nq2}).
#define SEG(CPTR, DV2) do {                                                \
        ulonglong2 c_ = *(CPTR);                                           \
        u64 u0 = fma2(xp[jj + 0], c_.x, c_.y);                             \
        u64 u1 = fma2(xp[jj + 1], c_.x, c_.y);                             \
        u64 u2 = fma2(xp[jj + 2], c_.x, c_.y);                             \
        u64 u3 = fma2(xp[jj + 3], c_.x, c_.y);                             \
        u0 = sat2(u0);                                                     \
        u1 = sat2(u1);                                                     \
        u2 = sat2(u2);                                                     \
        u3 = sat2(u3);                                                     \
        acc0 = fma2(u0, (DV2), acc0);                                      \
        acc1 = fma2(u1, (DV2), acc1);                                      \
        acc2 = fma2(u2, (DV2), acc2);                                      \
        acc3 = fma2(u3, (DV2), acc3);                                      \
    } while (0)

#pragma unroll
    for (int cc = 0; cc < 4; cc++) {
        __syncwarp();                      // prev reads done before overwrite
        FILL(xc);
        xc += HW_ * HW_;
        __syncwarp();                      // tile visible

        const ulonglong2* tp = s_tab + (cBase + cc) * 9 * 6;
#pragma unroll
        for (int i = 0; i < 3; i++) {
            // 6 x-pairs for this tap row: 3 x LDS.128 (16B-aligned)
            u64 xp[6];
            {
                const ulonglong2* rp =
                    reinterpret_cast<const ulonglong2*>(tile + (rl + i) * TSP_ + xg);
                ulonglong2 a = rp[0], bq = rp[1], cq = rp[2];
                xp[0] = a.x;  xp[1] = a.y;
                xp[2] = bq.x; xp[3] = bq.y;
                xp[4] = cq.x; xp[5] = cq.y;
            }
#pragma unroll
            for (int jj = 0; jj < 3; jj++) {
                const ulonglong2* t6 = tp + (i * 3 + jj) * 6;
                ulonglong2 d01 = t6[4];    // {(dv0,dv0),(dv1,dv1)}
                ulonglong2 d23 = t6[5];    // {(dv2,dv2),(dv3,dv3)}
                SEG(t6 + 0, d01.x);        // JIT (inv,nq) loads keep live
                SEG(t6 + 1, d01.y);        // registers under the 48 cap
                SEG(t6 + 2, d23.x);
                SEG(t6 + 3, d23.y);
            }
        }
    }
#undef SEG
#undef FILL

    // ---- Phase 2: reduce across the 8 warps (red aliases s_x) ----
    __syncthreads();                       // all tile reads done
    red[(warp * 32 + lane) * 4 + 0] = acc0;
    red[(warp * 32 + lane) * 4 + 1] = acc1;
    red[(warp * 32 + lane) * 4 + 2] = acc2;
    red[(warp * 32 + lane) * 4 + 3] = acc3;
    __syncthreads();

    if (tid < 32) {
        u64 r0 = 0ull, r1 = 0ull, r2 = 0ull, r3 = 0ull;
#pragma unroll
        for (int w = 0; w < 8; w++) {
            const ulonglong2* q = reinterpret_cast<const ulonglong2*>(red + (w * 32 + tid) * 4);
            ulonglong2 qa = q[0], qb = q[1];
            r0 = add2(r0, qa.x); r1 = add2(r1, qa.y);
            r2 = add2(r2, qb.x); r3 = add2(r3, qb.y);
        }
        float bias = s_bias;
        u64 bias2 = pk(bias, bias);
        r0 = add2(r0, bias2); r1 = add2(r1, bias2);
        r2 = add2(r2, bias2); r3 = add2(r3, bias2);
        float l0, h0, l1, h1, l2, h2, l3, h3;
        upk(l0, h0, r0); upk(l1, h1, r1); upk(l2, h2, r2); upk(l3, h3, r3);
        int rlo = tid >> 3;
        int col0 = (tid & 7) * 4;
        int base = ((b * O_ + o) * HW_ + y0) * HW_;
        *reinterpret_cast<float4*>(out + base + rlo * HW_ + col0) =
            make_float4(l0, l1, l2, l3);
        *reinterpret_cast<float4*>(out + base + (rlo + 4) * HW_ + col0) =
            make_float4(h0, h1, h2, h3);
    }
}

extern "C" void kernel_launch(void* const* d_in, const int* in_sizes, int n_in,
                              void* d_out, int out_size) {
    const float* x   = (const float*)d_in[0];
    const float* pos = (const float*)d_in[1];
    const float* val = (const float*)d_in[2];
    float* out = (float*)d_out;

    pc_fused<<<B_ * O_ * 4, 256>>>(x, pos, val, out);
}

// round 14
// speedup vs baseline: 1.1511x; 1.1511x over previous
#include <cuda_runtime.h>

#define B_  4
#define O_  32
#define C_  32
#define HW_ 32
#define P_  5
#define T_  288           // taps per output channel
#define EPSF 1e-6f
#define TSP_ 34           // pair-row stride in u64 (even -> 16B-aligned LDS.128)

typedef unsigned long long u64;

#define TILE_U64   (6 * TSP_)                    // 204 u64 per tile
#define TAB_BYTES  (T_ * 6 * 16)                 // 27648
#define TILES_BYTES (8 * 2 * TILE_U64 * 8)       // 26112 (2 buffers/warp)
#define SMEM_BYTES (TAB_BYTES + TILES_BYTES + 16)

__device__ __forceinline__ u64 pk(float lo, float hi) {
    u64 r; asm("mov.b64 %0, {%1, %2};" : "=l"(r) : "f"(lo), "f"(hi)); return r;
}
__device__ __forceinline__ void upk(float& lo, float& hi, u64 v) {
    asm("mov.b64 {%0, %1}, %2;" : "=f"(lo), "=f"(hi) : "l"(v));
}
__device__ __forceinline__ u64 fma2(u64 a, u64 b, u64 c) {
    u64 d; asm("fma.rn.f32x2 %0, %1, %2, %3;" : "=l"(d) : "l"(a), "l"(b), "l"(c));
    return d;
}
__device__ __forceinline__ u64 add2(u64 a, u64 b) {
    u64 d; asm("add.rn.f32x2 %0, %1, %2;" : "=l"(d) : "l"(a), "l"(b));
    return d;
}
// Per-half saturate via rt-1 immediate-form FFMA.SAT (validated, rel_err ~3e-7)
__device__ __forceinline__ u64 sat2(u64 u) {
    u64 s;
    asm("{\n\t"
        ".reg .f32 lo, hi;\n\t"
        "mov.b64 {lo, hi}, %1;\n\t"
        "fma.rn.sat.f32 lo, lo, 0f3F800000, 0f00000000;\n\t"
        "fma.rn.sat.f32 hi, hi, 0f3F800000, 0f00000000;\n\t"
        "mov.b64 %0, {lo, hi};\n\t"
        "}" : "=l"(s) : "l"(u));
    return s;
}
// 4-byte async copy global->shared; ok==0 => zero-fill (free boundary padding)
__device__ __forceinline__ void cpa4(unsigned dst, const float* src, int ok) {
    asm volatile("cp.async.ca.shared.global [%0], [%1], 4, %2;"
                 :: "r"(dst), "l"(src), "r"(ok ? 4 : 0) : "memory");
}

// ---------------------------------------------------------------------------
// R12 packed vertical-pair kernel + cp.async double-buffered tile prefetch.
// FILL is now 14 cp.async (zero registers, zero stall) issued into the other
// buffer BEFORE the current channel's ~2K-cycle math; waited at the channel
// boundary -> the per-channel LDG convoy stall (~400-600cyc x4) disappears.
// Pixels paired vertically at stride 4 (rows r, r+4 of an 8-row strip); all
// operands natively u64. Math/2px-seg: FFMA2 + 2x FFMA.SAT(rt-1) + FFMA2.
// Grid 512 = (b, o, 8-row strip); block 256 = 8 warps; warp = 4 channels,
// 8 px/thread. Dynamic smem 52.5KB (tables 27.6K dup + 2x8 tiles 25.5K).
// ---------------------------------------------------------------------------
__global__ __launch_bounds__(256, 4) void pc_fused(const float* __restrict__ x,
                                                   const float* __restrict__ pos,
                                                   const float* __restrict__ val,
                                                   float* __restrict__ out) {
    extern __shared__ __align__(16) char smem[];
    ulonglong2* s_tab  = reinterpret_cast<ulonglong2*>(smem);
    u64*        s_tile = reinterpret_cast<u64*>(smem + TAB_BYTES);
    float*      s_v0   = reinterpret_cast<float*>(s_tile);         // alias: dead
    u64*        red    = s_tile;                                   //  before use
    float*      s_bias = reinterpret_cast<float*>(smem + TAB_BYTES + TILES_BYTES);

    const int blk = blockIdx.x;
    const int quarter = blk & 3;           // 8-row strip
    const int o = (blk >> 2) & 31;
    const int b = blk >> 7;
    const int y0 = quarter * 8;

    const int tid = threadIdx.x;

    // ---- Phase 0: sort + duplicated coefficient tables ----
    const float* pbase = pos + o * (T_ * P_);
    const float* vbase = val + o * (T_ * P_);
#pragma unroll
    for (int rep = 0; rep < 2; rep++) {
        int ot = tid + rep * 256;
        if (ot < T_) {
            float p[P_], v[P_];
#pragma unroll
            for (int k = 0; k < P_; k++) { p[k] = pbase[ot * P_ + k]; v[k] = vbase[ot * P_ + k]; }
#define CE(a, bb) do { if (p[a] > p[bb]) { float t0 = p[a]; p[a] = p[bb]; p[bb] = t0; \
                                           float t1 = v[a]; v[a] = v[bb]; v[bb] = t1; } } while (0)
            CE(0,1); CE(3,4); CE(2,4); CE(2,3); CE(1,4); CE(0,3); CE(0,2); CE(1,3); CE(1,2);
#undef CE
            float* tf = (float*)(s_tab + ot * 6);   // 24 floats per tap
#pragma unroll
            for (int k = 0; k < 4; k++) {
                float den = p[k + 1] - p[k] + EPSF;
                float inv = 1.0f / den;
                float nq  = -p[k] * inv;
                float dv  = v[k + 1] - v[k];
                tf[4 * k + 0] = inv; tf[4 * k + 1] = inv;
                tf[4 * k + 2] = nq;  tf[4 * k + 3] = nq;
                tf[16 + 2 * k + 0] = dv; tf[16 + 2 * k + 1] = dv;
            }
            s_v0[ot] = v[0];
        }
    }
    __syncthreads();

    if (tid < 32) {        // bias = sum_t v0
        float s = 0.0f;
#pragma unroll
        for (int k = 0; k < 9; k++) s += s_v0[tid + k * 32];
#pragma unroll
        for (int off = 16; off > 0; off >>= 1) s += __shfl_down_sync(0xffffffffu, s, off);
        if (tid == 0) *s_bias = s;
    }
    __syncthreads();       // also: v0 alias dead from here; tiles may be written

    // ---- Phase 1 ----
    const int warp = tid >> 5;
    const int lane = tid & 31;
    const int rl   = lane >> 3;            // 0..3: pair row group (rows rl, rl+4)
    const int xg   = (lane & 7) * 4;       // 0,4,...,28
    const int gxc  = (lane >= 1) ? (lane - 1) : 0;

    u64 acc0 = 0ull, acc1 = 0ull, acc2 = 0ull, acc3 = 0ull;

    const float* xb = x + b * (C_ * HW_ * HW_);
    const int cBase = warp * 4;            // 4 channels per warp
    const float* xc = xb + cBase * (HW_ * HW_);
    u64* tA = s_tile + warp * 2 * TILE_U64;
    u64* tB = tA + TILE_U64;
    const unsigned tA32 = (unsigned)__cvta_generic_to_shared(tA);
    const unsigned tB32 = tA32 + TILE_U64 * 8;

    // constant OOB column 33 (gx=32): zero once for both buffers
    if (lane < 6) { tA[lane * TSP_ + 33] = 0ull; tB[lane * TSP_ + 33] = 0ull; }

// Async fill of one packed tile: pair-row k = (x[y0+k-1], x[y0+k+3]), col gx.
#define FILLA(TD, XC) do {                                                 \
    const float* xp_ = (XC);                                               \
    _Pragma("unroll")                                                      \
    for (int k = 0; k < 6; k++) {                                          \
        int gyL_ = y0 + k - 1;                                             \
        int gyH_ = y0 + k + 3;                                             \
        int okL_ = (lane >= 1) && (gyL_ >= 0);                             \
        int okH_ = (lane >= 1) && (gyH_ < HW_);                            \
        unsigned d_ = (TD) + (unsigned)((k * TSP_ + lane) * 8);            \
        cpa4(d_,     xp_ + (gyL_ >= 0 ? gyL_ : 0) * HW_ + gxc, okL_);      \
        cpa4(d_ + 4, xp_ + (gyH_ < HW_ ? gyH_ : 0) * HW_ + gxc, okH_);     \
    }                                                                      \
    if (lane < 6) {                                                        \
        int gyL_ = y0 + lane - 1;                                          \
        int gyH_ = y0 + lane + 3;                                          \
        unsigned d_ = (TD) + (unsigned)((lane * TSP_ + 32) * 8);           \
        cpa4(d_,     xp_ + (gyL_ >= 0 ? gyL_ : 0) * HW_ + 31, gyL_ >= 0);  \
        cpa4(d_ + 4, xp_ + (gyH_ < HW_ ? gyH_ : 0) * HW_ + 31, gyH_ < HW_);\
    }                                                                      \
    asm volatile("cp.async.commit_group;" ::: "memory");                   \
} while (0)

// One segment, 4 pixel-pairs: FFMA2 + sat2 + FFMA2 each.
#define SEG(IV2, NQ2, DV2) do {                                            \
        u64 u0 = fma2(xp[jj + 0], (IV2), (NQ2));                           \
        u64 u1 = fma2(xp[jj + 1], (IV2), (NQ2));                           \
        u64 u2 = fma2(xp[jj + 2], (IV2), (NQ2));                           \
        u64 u3 = fma2(xp[jj + 3], (IV2), (NQ2));                           \
        u0 = sat2(u0);                                                     \
        u1 = sat2(u1);                                                     \
        u2 = sat2(u2);                                                     \
        u3 = sat2(u3);                                                     \
        acc0 = fma2(u0, (DV2), acc0);                                      \
        acc1 = fma2(u1, (DV2), acc1);                                      \
        acc2 = fma2(u2, (DV2), acc2);                                      \
        acc3 = fma2(u3, (DV2), acc3);                                      \
    } while (0)

    // prologue: fill channel 0 into tA
    FILLA(tA32, xc);
    asm volatile("cp.async.wait_group 0;" ::: "memory");
    __syncwarp();

    for (int cc = 0; cc < 4; cc++) {
        u64* cur = (cc & 1) ? tB : tA;
        unsigned nxt32 = (cc & 1) ? tA32 : tB32;

        if (cc < 3) FILLA(nxt32, xc + HW_ * HW_);   // overlaps math below
        xc += HW_ * HW_;

        const ulonglong2* tp = s_tab + (cBase + cc) * 9 * 6;
#pragma unroll
        for (int i = 0; i < 3; i++) {
            // 6 x-pairs for this tap row: 3 x LDS.128 (16B-aligned)
            u64 xp[6];
            {
                const ulonglong2* rp =
                    reinterpret_cast<const ulonglong2*>(cur + (rl + i) * TSP_ + xg);
                ulonglong2 a = rp[0], bq = rp[1], cq = rp[2];
                xp[0] = a.x;  xp[1] = a.y;
                xp[2] = bq.x; xp[3] = bq.y;
                xp[4] = cq.x; xp[5] = cq.y;
            }
#pragma unroll
            for (int jj = 0; jj < 3; jj++) {
                const ulonglong2* t6 = tp + (i * 3 + jj) * 6;
                ulonglong2 c0 = t6[0];     // {(inv0,inv0),(nq0,nq0)} broadcast
                ulonglong2 c1 = t6[1];
                ulonglong2 c2 = t6[2];
                ulonglong2 c3 = t6[3];
                ulonglong2 d01 = t6[4];    // {(dv0,dv0),(dv1,dv1)}
                ulonglong2 d23 = t6[5];    // {(dv2,dv2),(dv3,dv3)}
                SEG(c0.x, c0.y, d01.x);
                SEG(c1.x, c1.y, d01.y);
                SEG(c2.x, c2.y, d23.x);
                SEG(c3.x, c3.y, d23.y);
            }
        }

        asm volatile("cp.async.wait_group 0;" ::: "memory");
        __syncwarp();                      // next tile ready; prev reads done
    }
#undef SEG
#undef FILLA

    // ---- Phase 2: reduce across the 8 warps (red aliases tiles) ----
    __syncthreads();                       // all tile reads done everywhere
    red[(warp * 32 + lane) * 4 + 0] = acc0;
    red[(warp * 32 + lane) * 4 + 1] = acc1;
    red[(warp * 32 + lane) * 4 + 2] = acc2;
    red[(warp * 32 + lane) * 4 + 3] = acc3;
    __syncthreads();

    if (tid < 32) {
        u64 r0 = 0ull, r1 = 0ull, r2 = 0ull, r3 = 0ull;
#pragma unroll
        for (int w = 0; w < 8; w++) {
            const ulonglong2* q = reinterpret_cast<const ulonglong2*>(red + (w * 32 + tid) * 4);
            ulonglong2 qa = q[0], qb = q[1];
            r0 = add2(r0, qa.x); r1 = add2(r1, qa.y);
            r2 = add2(r2, qb.x); r3 = add2(r3, qb.y);
        }
        float bias = *s_bias;
        u64 bias2 = pk(bias, bias);
        r0 = add2(r0, bias2); r1 = add2(r1, bias2);
        r2 = add2(r2, bias2); r3 = add2(r3, bias2);
        float l0, h0, l1, h1, l2, h2, l3, h3;
        upk(l0, h0, r0); upk(l1, h1, r1); upk(l2, h2, r2); upk(l3, h3, r3);
        int rlo = tid >> 3;
        int col0 = (tid & 7) * 4;
        int base = ((b * O_ + o) * HW_ + y0) * HW_;
        *reinterpret_cast<float4*>(out + base + rlo * HW_ + col0) =
            make_float4(l0, l1, l2, l3);
        *reinterpret_cast<float4*>(out + base + (rlo + 4) * HW_ + col0) =
            make_float4(h0, h1, h2, h3);
    }
}

extern "C" void kernel_launch(void* const* d_in, const int* in_sizes, int n_in,
                              void* d_out, int out_size) {
    const float* x   = (const float*)d_in[0];
    const float* pos = (const float*)d_in[1];
    const float* val = (const float*)d_in[2];
    float* out = (float*)d_out;

    cudaFuncSetAttribute(pc_fused, cudaFuncAttributeMaxDynamicSharedMemorySize,
                         SMEM_BYTES);
    pc_fused<<<B_ * O_ * 4, 256, SMEM_BYTES>>>(x, pos, val, out);
}